// round 4
// baseline (speedup 1.0000x reference)
#include <cuda_runtime.h>

// Inverse 3D Haar synthesis:
//   in  : [B=2, 8*16, T=8, H=128, W=128] fp32 (8 subbands of 16 channels)
//   out : [B=2, 16, 16, 256, 256] fp32
// out[b,g,2t+pt,2h+ph,2w+pw] = (1/8) * sum_s (-1)^(bt*pt+bh*ph+bw*pw) * x[b, s*16+g, t, h, w]
// with s = 4*bt + 2*bh + bw.
//
// Each thread owns 2 consecutive input w (float2) on TWO consecutive h rows:
// 16 front-batched LDG.64 (MLP=16) to hide DRAM latency. Every (pt,ph,h) output
// row is 4 contiguous floats -> STG.128 at lane-stride 16B (dense 512B/warp).

__device__ __forceinline__ float2 f2add(float2 a, float2 b) {
    return make_float2(a.x + b.x, a.y + b.y);
}
__device__ __forceinline__ float2 f2sub(float2 a, float2 b) {
    return make_float2(a.x - b.x, a.y - b.y);
}

__global__ __launch_bounds__(256) void ihaar3d_kernel(const float* __restrict__ x,
                                                      float* __restrict__ out) {
    // Decode: [b(1)][g(4)][t(3)][hp(6)][w2(6)] bits -> 2^20 threads.
    const int idx = blockIdx.x * blockDim.x + threadIdx.x;
    const int w2 = idx & 63;           // which pair of input w
    const int hp = (idx >> 6) & 63;    // which pair of input h rows
    const int t  = (idx >> 12) & 7;
    const int g  = (idx >> 15) & 15;
    const int b  = (idx >> 19) & 1;

    const int w0 = w2 << 1;
    const int h0 = hp << 1;

    // input: [B, 128, 8, 128, 128]; subband stride = 16 channels. Offsets fit int32.
    const int SUB = 16 * 8 * 128 * 128;  // 2,097,152
    const int HS = 128;                  // h stride in input
    const int base = (((b * 128 + g) * 8 + t) * 128 + h0) * 128 + w0;

    // Front-batched loads: 8 subbands x 2 h rows = 16 independent LDG.64.
    float2 va[8], vb[8];
#pragma unroll
    for (int s = 0; s < 8; ++s) {
        va[s] = *reinterpret_cast<const float2*>(x + base + s * SUB);
        vb[s] = *reinterpret_cast<const float2*>(x + base + s * SUB + HS);
    }

    // out: [2, 16, 16, 256, 256]; offsets fit int32.
    const float k = 0.125f;
    const int PT = 256 * 256;
    const int PH = 256;
    const int obase = (((b * 16 + g) * 16 + 2 * t) * 256 + 2 * h0) * 256 + 2 * w0;

#pragma unroll
    for (int r = 0; r < 2; ++r) {
        const float2* v = (r == 0) ? va : vb;
        const int ob = obase + r * (2 * PH);

        // Stage 1: W butterfly (bit0).
        float2 ll_e = f2add(v[0], v[1]), ll_o = f2sub(v[0], v[1]);
        float2 lh_e = f2add(v[2], v[3]), lh_o = f2sub(v[2], v[3]);
        float2 hl_e = f2add(v[4], v[5]), hl_o = f2sub(v[4], v[5]);
        float2 hh_e = f2add(v[6], v[7]), hh_o = f2sub(v[6], v[7]);

        // Stage 2: H butterfly (bit1): index = ph.
        float2 le[2] = {f2add(ll_e, lh_e), f2sub(ll_e, lh_e)};
        float2 lo[2] = {f2add(ll_o, lh_o), f2sub(ll_o, lh_o)};
        float2 he[2] = {f2add(hl_e, hh_e), f2sub(hl_e, hh_e)};
        float2 ho[2] = {f2add(hl_o, hh_o), f2sub(hl_o, hh_o)};

        // Stage 3: T butterfly (bit2) + scale + interleaved store.
#pragma unroll
        for (int pt = 0; pt < 2; ++pt) {
#pragma unroll
            for (int ph = 0; ph < 2; ++ph) {
                float2 e = pt == 0 ? f2add(le[ph], he[ph]) : f2sub(le[ph], he[ph]);
                float2 o = pt == 0 ? f2add(lo[ph], ho[ph]) : f2sub(lo[ph], ho[ph]);
                *reinterpret_cast<float4*>(out + ob + pt * PT + ph * PH) =
                    make_float4(e.x * k, o.x * k, e.y * k, o.y * k);
            }
        }
    }
}

extern "C" void kernel_launch(void* const* d_in, const int* in_sizes, int n_in,
                              void* d_out, int out_size) {
    const float* x = (const float*)d_in[0];
    float* out = (float*)d_out;
    // total threads = 2*16*8*64*64 = 1,048,576
    ihaar3d_kernel<<<4096, 256>>>(x, out);
}

// round 5
// speedup vs baseline: 1.0530x; 1.0530x over previous
#include <cuda_runtime.h>

// Inverse 3D Haar synthesis:
//   in  : [B=2, 8*16, T=8, H=128, W=128] fp32 (8 subbands of 16 channels)
//   out : [B=2, 16, 16, 256, 256] fp32
// out[b,g,2t+pt,2h+ph,2w+pw] = (1/8) * sum_s (-1)^(bt*pt+bh*ph+bw*pw) * x[b, s*16+g, t, h, w]
// with s = 4*bt + 2*bh + bw.
//
// One thread owns 2 consecutive input w (LDG.64 coalesced). Each (pt,ph) output
// row is 4 contiguous floats -> one STG.128 at lane-stride 16B (dense 512B/warp).
// Stores use evict-first streaming (__stcs) so output lines don't displace the
// 134MB input working set from the 126MB L2 across graph replays.

__device__ __forceinline__ float2 f2add(float2 a, float2 b) {
    return make_float2(a.x + b.x, a.y + b.y);
}
__device__ __forceinline__ float2 f2sub(float2 a, float2 b) {
    return make_float2(a.x - b.x, a.y - b.y);
}

__global__ __launch_bounds__(256) void ihaar3d_kernel(const float* __restrict__ x,
                                                      float* __restrict__ out) {
    // Linear decode: [b(1)][g(4)][t(3)][h(7)][w2(6)] bits -> 2^21 threads.
    const int idx = blockIdx.x * blockDim.x + threadIdx.x;
    const int w2 = idx & 63;          // which pair of input w
    const int h  = (idx >> 6) & 127;
    const int t  = (idx >> 13) & 7;
    const int g  = (idx >> 16) & 15;
    const int b  = (idx >> 20) & 1;

    const int w0 = w2 << 1;  // input w of first element

    // input: [B, 128, 8, 128, 128]; subband stride = 16 channels. Offsets fit int32.
    const int SUB = 16 * 8 * 128 * 128;  // 2,097,152
    const int base = (((b * 128 + g) * 8 + t) * 128 + h) * 128 + w0;

    float2 v0 = *reinterpret_cast<const float2*>(x + base + 0 * SUB);  // lll
    float2 v1 = *reinterpret_cast<const float2*>(x + base + 1 * SUB);  // llh
    float2 v2 = *reinterpret_cast<const float2*>(x + base + 2 * SUB);  // lhl
    float2 v3 = *reinterpret_cast<const float2*>(x + base + 3 * SUB);  // lhh
    float2 v4 = *reinterpret_cast<const float2*>(x + base + 4 * SUB);  // hll
    float2 v5 = *reinterpret_cast<const float2*>(x + base + 5 * SUB);  // hlh
    float2 v6 = *reinterpret_cast<const float2*>(x + base + 6 * SUB);  // hhl
    float2 v7 = *reinterpret_cast<const float2*>(x + base + 7 * SUB);  // hhh

    // Stage 1: W butterfly (bit0): e = even W parity, o = odd W parity.
    float2 ll_e = f2add(v0, v1), ll_o = f2sub(v0, v1);
    float2 lh_e = f2add(v2, v3), lh_o = f2sub(v2, v3);
    float2 hl_e = f2add(v4, v5), hl_o = f2sub(v4, v5);
    float2 hh_e = f2add(v6, v7), hh_o = f2sub(v6, v7);

    // Stage 2: H butterfly (bit1): index = ph.
    float2 l0e = f2add(ll_e, lh_e), l1e = f2sub(ll_e, lh_e);
    float2 l0o = f2add(ll_o, lh_o), l1o = f2sub(ll_o, lh_o);
    float2 h0e = f2add(hl_e, hh_e), h1e = f2sub(hl_e, hh_e);
    float2 h0o = f2add(hl_o, hh_o), h1o = f2sub(hl_o, hh_o);

    // Stage 3: T butterfly (bit2) + scale + evict-first streaming store.
    // out: [2, 16, 16, 256, 256]; offsets fit int32.
    const float k = 0.125f;
    const int obase = (((b * 16 + g) * 16 + 2 * t) * 256 + 2 * h) * 256 + 2 * w0;
    const int PT = 256 * 256;
    const int PH = 256;

    float2 le[2] = {l0e, l1e}, lo[2] = {l0o, l1o};
    float2 he[2] = {h0e, h1e}, ho[2] = {h0o, h1o};

#pragma unroll
    for (int pt = 0; pt < 2; ++pt) {
#pragma unroll
        for (int ph = 0; ph < 2; ++ph) {
            float2 e = pt == 0 ? f2add(le[ph], he[ph]) : f2sub(le[ph], he[ph]);
            float2 o = pt == 0 ? f2add(lo[ph], ho[ph]) : f2sub(lo[ph], ho[ph]);
            __stcs(reinterpret_cast<float4*>(out + obase + pt * PT + ph * PH),
                   make_float4(e.x * k, o.x * k, e.y * k, o.y * k));
        }
    }
}

extern "C" void kernel_launch(void* const* d_in, const int* in_sizes, int n_in,
                              void* d_out, int out_size) {
    const float* x = (const float*)d_in[0];
    float* out = (float*)d_out;
    // total threads = 2*16*8*128*64 = 2,097,152
    ihaar3d_kernel<<<8192, 256>>>(x, out);
}